// round 1
// baseline (speedup 1.0000x reference)
#include <cuda_runtime.h>
#include <cstdint>

// ---------------- problem constants ----------------
#define B_      2
#define S_      4096
#define H_      2048
#define NH_     16
#define NKV_    4
#define D_      128
#define BS_     64
#define KB_     (S_ / BS_)      // 64 key blocks
#define NGLOB_  4
#define NLOCAL_ 8
#define NSEL_   (NGLOB_ + NLOCAL_)   // 12
#define STRIDE_ 16
#define NTOK_   (B_ * S_)       // 8192
#define QDIM_   (NH_ * D_)      // 2048
#define KVDIM_  (NKV_ * D_)     // 512
#define SCALE_  0.088388347648318447f   // 1/sqrt(128)
#define NEG_    (-1000000000.0f)

// ---------------- scratch (static device globals; no runtime alloc) -------
__device__ float g_q[(size_t)NTOK_ * QDIM_];     // 64 MB
__device__ float g_k[(size_t)NTOK_ * KVDIM_];    // 16 MB
__device__ float g_v[(size_t)NTOK_ * KVDIM_];    // 16 MB
__device__ float g_attn[(size_t)NTOK_ * QDIM_];  // 64 MB

// ---------------- GEMM:  C[M,N] = A[M,K] @ B[N,K]^T  (all row-major) ------
// 128x128 block tile, BK=8, 8x8 per-thread microtile, 256 threads.
__global__ void __launch_bounds__(256)
gemm_nt_kernel(const float* __restrict__ A, const float* __restrict__ B,
               float* __restrict__ C, int M, int N, int K)
{
    __shared__ float As[8][128];
    __shared__ float Bs[8][128];

    const int bm = blockIdx.y * 128;
    const int bn = blockIdx.x * 128;
    const int t  = threadIdx.x;

    const int lrow = t >> 1;          // 0..127
    const int lcol = (t & 1) << 2;    // 0 or 4
    const float* Ap = A + (size_t)(bm + lrow) * K + lcol;
    const float* Bp = B + (size_t)(bn + lrow) * K + lcol;

    const int tx = t & 15;            // 0..15  -> N microtile
    const int ty = t >> 4;            // 0..15  -> M microtile

    float acc[8][8];
#pragma unroll
    for (int i = 0; i < 8; i++)
#pragma unroll
        for (int j = 0; j < 8; j++) acc[i][j] = 0.0f;

    for (int k0 = 0; k0 < K; k0 += 8) {
        float4 av = *(const float4*)(Ap + k0);
        float4 bv = *(const float4*)(Bp + k0);
        __syncthreads();
        As[lcol + 0][lrow] = av.x;
        As[lcol + 1][lrow] = av.y;
        As[lcol + 2][lrow] = av.z;
        As[lcol + 3][lrow] = av.w;
        Bs[lcol + 0][lrow] = bv.x;
        Bs[lcol + 1][lrow] = bv.y;
        Bs[lcol + 2][lrow] = bv.z;
        Bs[lcol + 3][lrow] = bv.w;
        __syncthreads();
#pragma unroll
        for (int k = 0; k < 8; k++) {
            float4 a0 = *(const float4*)&As[k][ty * 8];
            float4 a1 = *(const float4*)&As[k][ty * 8 + 4];
            float4 b0 = *(const float4*)&Bs[k][tx * 8];
            float4 b1 = *(const float4*)&Bs[k][tx * 8 + 4];
            float ra[8] = {a0.x, a0.y, a0.z, a0.w, a1.x, a1.y, a1.z, a1.w};
            float rb[8] = {b0.x, b0.y, b0.z, b0.w, b1.x, b1.y, b1.z, b1.w};
#pragma unroll
            for (int i = 0; i < 8; i++)
#pragma unroll
                for (int j = 0; j < 8; j++)
                    acc[i][j] += ra[i] * rb[j];
        }
    }

#pragma unroll
    for (int i = 0; i < 8; i++) {
        float* cp = C + (size_t)(bm + ty * 8 + i) * N + bn + tx * 8;
        *(float4*)cp       = make_float4(acc[i][0], acc[i][1], acc[i][2], acc[i][3]);
        *(float4*)(cp + 4) = make_float4(acc[i][4], acc[i][5], acc[i][6], acc[i][7]);
    }
}

// ---------------- RoPE (in-place on g_q, g_k) -----------------------------
// one thread per (token, head, d<64) pair; handles (d, d+64) together.
__global__ void rope_kernel(const float* __restrict__ cosp,
                            const float* __restrict__ sinp)
{
    int idx = blockIdx.x * blockDim.x + threadIdx.x;
    const int total = NTOK_ * (NH_ + NKV_) * (D_ / 2);
    if (idx >= total) return;

    int d    = idx % (D_ / 2);
    int rest = idx / (D_ / 2);
    int h    = rest % (NH_ + NKV_);
    int tok  = rest / (NH_ + NKV_);

    float c1 = cosp[(size_t)tok * D_ + d];
    float s1 = sinp[(size_t)tok * D_ + d];
    float c2 = cosp[(size_t)tok * D_ + d + D_ / 2];
    float s2 = sinp[(size_t)tok * D_ + d + D_ / 2];

    float* buf;
    if (h < NH_) buf = g_q + (size_t)tok * QDIM_ + h * D_;
    else         buf = g_k + (size_t)tok * KVDIM_ + (h - NH_) * D_;

    float x1 = buf[d];
    float x2 = buf[d + D_ / 2];
    buf[d]           = x1 * c1 - x2 * s1;
    buf[d + D_ / 2]  = x2 * c2 + x1 * s2;
}

// ---------------- block-sparse attention ----------------------------------
// grid: (qblock=64, head=16, batch=2); 256 threads.
// smem: Qs[64][128] + KVs[64][128] + Ss[64][65] + row stats = 82944 bytes.
#define ATTN_SMEM_FLOATS (64 * 128 + 64 * 128 + 64 * 65 + 3 * 64)
#define ATTN_SMEM_BYTES  (ATTN_SMEM_FLOATS * 4)

__global__ void __launch_bounds__(256)
attn_kernel()
{
    extern __shared__ float sm[];
    float* Qs   = sm;                       // 64*128
    float* KVs  = Qs + 64 * 128;            // 64*128 (K, then reused for V)
    float* Ss   = KVs + 64 * 128;           // 64*65 (padded)
    float* rowm = Ss + 64 * 65;             // 64
    float* rowl = rowm + 64;                // 64
    float* rowf = rowl + 64;                // 64
    __shared__ int sel_s[NSEL_];
    __shared__ int keep_s[NSEL_];

    const int qid = blockIdx.x;
    const int h   = blockIdx.y;
    const int b   = blockIdx.z;
    const int t   = threadIdx.x;
    const int kvh = h / (NH_ / NKV_);

    // load Q block
    const float* qptr = g_q + ((size_t)(b * S_ + qid * BS_)) * QDIM_ + h * D_;
    for (int i = t; i < BS_ * D_; i += 256) {
        int r = i >> 7, d = i & 127;
        Qs[i] = qptr[(size_t)r * QDIM_ + d];
    }

    // block selection + dedup (matches reference exactly)
    if (t < NSEL_) {
        int s;
        if (t < NGLOB_) { s = t * STRIDE_; if (s > KB_ - 1) s = KB_ - 1; }
        else            { int j = t - NGLOB_; s = qid - (NLOCAL_ - 1) + j;
                          s = s < 0 ? 0 : (s > KB_ - 1 ? KB_ - 1 : s); }
        bool valid = (s <= qid);
        bool dup = false;
        for (int jj = 0; jj < t; jj++) {
            int sj;
            if (jj < NGLOB_) { sj = jj * STRIDE_; if (sj > KB_ - 1) sj = KB_ - 1; }
            else             { int j2 = jj - NGLOB_; sj = qid - (NLOCAL_ - 1) + j2;
                               sj = sj < 0 ? 0 : (sj > KB_ - 1 ? KB_ - 1 : sj); }
            if (sj == s) dup = true;
        }
        sel_s[t]  = s;
        keep_s[t] = (valid && !dup) ? 1 : 0;
    }
    if (t < 64) { rowm[t] = -1e30f; rowl[t] = 0.0f; }

    float acc[32];
#pragma unroll
    for (int i = 0; i < 32; i++) acc[i] = 0.0f;

    const int tx = t & 15;        // score cols / output dims
    const int ty = t >> 4;        // rows
    const int r0 = ty * 4;        // 4 rows per thread
    const int c0 = tx * 4;        // 4 score cols per thread
    const int d0 = tx * 8;        // 8 output dims per thread

    __syncthreads();

    for (int bi = 0; bi < NSEL_; bi++) {
        if (!keep_s[bi]) continue;
        const int kblk = sel_s[bi];
        const bool diag = (kblk == qid);

        // load K block
        const float* kptr = g_k + ((size_t)(b * S_ + kblk * BS_)) * KVDIM_ + kvh * D_;
        for (int i = t; i < BS_ * D_; i += 256) {
            int r = i >> 7, d = i & 127;
            KVs[i] = kptr[(size_t)r * KVDIM_ + d];
        }
        __syncthreads();

        // scores: 4x4 microtile per thread
        float sc[4][4];
#pragma unroll
        for (int i = 0; i < 4; i++)
#pragma unroll
            for (int j = 0; j < 4; j++) sc[i][j] = 0.0f;

        for (int d = 0; d < D_; d += 4) {
            float4 qa[4], kb4[4];
#pragma unroll
            for (int i = 0; i < 4; i++) qa[i]  = *(const float4*)&Qs[(r0 + i) * D_ + d];
#pragma unroll
            for (int j = 0; j < 4; j++) kb4[j] = *(const float4*)&KVs[(c0 + j) * D_ + d];
#pragma unroll
            for (int i = 0; i < 4; i++)
#pragma unroll
                for (int j = 0; j < 4; j++)
                    sc[i][j] += qa[i].x * kb4[j].x + qa[i].y * kb4[j].y +
                                qa[i].z * kb4[j].z + qa[i].w * kb4[j].w;
        }
#pragma unroll
        for (int i = 0; i < 4; i++)
#pragma unroll
            for (int j = 0; j < 4; j++) {
                float v = sc[i][j] * SCALE_;
                if (diag && (c0 + j) > (r0 + i)) v += NEG_;
                Ss[(r0 + i) * 65 + (c0 + j)] = v;
            }
        __syncthreads();

        // online softmax update (one thread per query row)
        if (t < 64) {
            float m_old = rowm[t];
            float mx = m_old;
            for (int k = 0; k < 64; k++) mx = fmaxf(mx, Ss[t * 65 + k]);
            float f = __expf(m_old - mx);
            float sum = 0.0f;
            for (int k = 0; k < 64; k++) {
                float p = __expf(Ss[t * 65 + k] - mx);
                Ss[t * 65 + k] = p;
                sum += p;
            }
            rowl[t] = rowl[t] * f + sum;
            rowm[t] = mx;
            rowf[t] = f;
        }
        __syncthreads();

        // rescale accumulator
        float fr[4];
#pragma unroll
        for (int i = 0; i < 4; i++) fr[i] = rowf[r0 + i];
#pragma unroll
        for (int i = 0; i < 4; i++)
#pragma unroll
            for (int j = 0; j < 8; j++) acc[i * 8 + j] *= fr[i];

        // load V block (reuse KVs)
        const float* vptr = g_v + ((size_t)(b * S_ + kblk * BS_)) * KVDIM_ + kvh * D_;
        for (int i = t; i < BS_ * D_; i += 256) {
            int r = i >> 7, d = i & 127;
            KVs[i] = vptr[(size_t)r * KVDIM_ + d];
        }
        __syncthreads();

        // P @ V: 4 rows x 8 dims per thread
        for (int k = 0; k < 64; k++) {
            float p[4];
#pragma unroll
            for (int i = 0; i < 4; i++) p[i] = Ss[(r0 + i) * 65 + k];
            float4 v0 = *(const float4*)&KVs[k * D_ + d0];
            float4 v1 = *(const float4*)&KVs[k * D_ + d0 + 4];
#pragma unroll
            for (int i = 0; i < 4; i++) {
                acc[i * 8 + 0] += p[i] * v0.x;
                acc[i * 8 + 1] += p[i] * v0.y;
                acc[i * 8 + 2] += p[i] * v0.z;
                acc[i * 8 + 3] += p[i] * v0.w;
                acc[i * 8 + 4] += p[i] * v1.x;
                acc[i * 8 + 5] += p[i] * v1.y;
                acc[i * 8 + 6] += p[i] * v1.z;
                acc[i * 8 + 7] += p[i] * v1.w;
            }
        }
        __syncthreads();   // before next iteration overwrites KVs / Ss
    }

    // finalize: divide by softmax denom, write out
    float invl[4];
#pragma unroll
    for (int i = 0; i < 4; i++) invl[i] = 1.0f / rowl[r0 + i];
#pragma unroll
    for (int i = 0; i < 4; i++) {
        float* op = g_attn + ((size_t)(b * S_ + qid * BS_ + r0 + i)) * QDIM_ + h * D_ + d0;
        float4 o0 = make_float4(acc[i*8+0]*invl[i], acc[i*8+1]*invl[i],
                                acc[i*8+2]*invl[i], acc[i*8+3]*invl[i]);
        float4 o1 = make_float4(acc[i*8+4]*invl[i], acc[i*8+5]*invl[i],
                                acc[i*8+6]*invl[i], acc[i*8+7]*invl[i]);
        *(float4*)op       = o0;
        *(float4*)(op + 4) = o1;
    }
}

// ---------------- host launcher -------------------------------------------
extern "C" void kernel_launch(void* const* d_in, const int* in_sizes, int n_in,
                              void* d_out, int out_size)
{
    const float* X    = (const float*)d_in[0];  // hidden_states [B,S,H]
    const float* cosp = (const float*)d_in[1];  // [B,S,D]
    const float* sinp = (const float*)d_in[2];  // [B,S,D]
    const float* Wq   = (const float*)d_in[3];  // [NH*D, H]
    const float* Wk   = (const float*)d_in[4];  // [NKV*D, H]
    const float* Wv   = (const float*)d_in[5];  // [NKV*D, H]
    const float* Wo   = (const float*)d_in[6];  // [H, NH*D]
    float* out = (float*)d_out;

    float *qb, *kb, *vb, *ab;
    cudaGetSymbolAddress((void**)&qb, g_q);
    cudaGetSymbolAddress((void**)&kb, g_k);
    cudaGetSymbolAddress((void**)&vb, g_v);
    cudaGetSymbolAddress((void**)&ab, g_attn);

    cudaFuncSetAttribute(attn_kernel,
                         cudaFuncAttributeMaxDynamicSharedMemorySize,
                         ATTN_SMEM_BYTES);

    // QKV projections
    gemm_nt_kernel<<<dim3(QDIM_ / 128, NTOK_ / 128), 256>>>(X, Wq, qb, NTOK_, QDIM_, H_);
    gemm_nt_kernel<<<dim3(KVDIM_ / 128, NTOK_ / 128), 256>>>(X, Wk, kb, NTOK_, KVDIM_, H_);
    gemm_nt_kernel<<<dim3(KVDIM_ / 128, NTOK_ / 128), 256>>>(X, Wv, vb, NTOK_, KVDIM_, H_);

    // RoPE on Q and K
    int rope_total = NTOK_ * (NH_ + NKV_) * (D_ / 2);
    rope_kernel<<<(rope_total + 255) / 256, 256>>>(cosp, sinp);

    // block-sparse attention
    attn_kernel<<<dim3(KB_, NH_, B_), 256, ATTN_SMEM_BYTES>>>();

    // output projection
    gemm_nt_kernel<<<dim3(H_ / 128, NTOK_ / 128), 256>>>(ab, Wo, out, NTOK_, H_, QDIM_);
}

// round 2
// speedup vs baseline: 1.5365x; 1.5365x over previous
#include <cuda_runtime.h>
#include <cstdint>

// ---------------- problem constants ----------------
#define B_      2
#define S_      4096
#define H_      2048
#define NH_     16
#define NKV_    4
#define D_      128
#define BS_     64
#define KB_     (S_ / BS_)      // 64 key blocks
#define NGLOB_  4
#define NLOCAL_ 8
#define NSEL_   (NGLOB_ + NLOCAL_)   // 12
#define STRIDE_ 16
#define NTOK_   (B_ * S_)       // 8192
#define QDIM_   (NH_ * D_)      // 2048
#define KVDIM_  (NKV_ * D_)     // 512
#define SCALE_  0.088388347648318447f   // 1/sqrt(128)
#define NEG_    (-1000000000.0f)

// ---------------- scratch (static device globals; no runtime alloc) -------
__device__ float g_q[(size_t)NTOK_ * QDIM_];     // 64 MB
__device__ float g_k[(size_t)NTOK_ * KVDIM_];    // 16 MB
__device__ float g_v[(size_t)NTOK_ * KVDIM_];    // 16 MB
__device__ float g_attn[(size_t)NTOK_ * QDIM_];  // 64 MB

// ---------------- tf32 tensor-core GEMM -----------------------------------
//  C[M,N] = A[M,K] @ B[N,K]^T   (row-major A, row-major B with K contiguous)
//  CTA tile 128x128, BK=16, 256 threads = 8 warps (2 along M x 4 along N),
//  warp tile 64x32 = 4x4 mma.m16n8k8 tiles. tf32 inputs via cvt.rna at the
//  smem-store, fp32 accumulate. Register double-buffered global loads.
#define LDT_ 132   // smem row stride (floats), padded

__device__ __forceinline__ uint32_t f2tf32(float x) {
    uint32_t u;
    asm("cvt.rna.tf32.f32 %0, %1;" : "=r"(u) : "f"(x));
    return u;
}

__global__ void __launch_bounds__(256, 2)
gemm_tf32_nt(const float* __restrict__ A, const float* __restrict__ B,
             float* __restrict__ C, int M, int N, int K)
{
    __shared__ uint32_t As[16 * LDT_];
    __shared__ uint32_t Bs[16 * LDT_];

    const int bm = blockIdx.y * 128;
    const int bn = blockIdx.x * 128;
    const int t  = threadIdx.x;

    // global load mapping: float4 id v -> row = v>>2, kc = (v&3)*4
    const int r0 = t >> 2;          // 0..63
    const int kc = (t & 3) << 2;    // 0,4,8,12
    const float* Ag = A + (size_t)(bm + r0) * K + kc;
    const float* Bg = B + (size_t)(bn + r0) * K + kc;

    const int lane = t & 31;
    const int warp = t >> 5;
    const int g  = lane >> 2;       // groupID 0..7
    const int tg = lane & 3;        // tid-in-group 0..3
    const int wm = (warp >> 2) * 64;
    const int wn = (warp & 3) * 32;

    float acc[4][4][4];
#pragma unroll
    for (int mi = 0; mi < 4; mi++)
#pragma unroll
        for (int ni = 0; ni < 4; ni++)
#pragma unroll
            for (int c = 0; c < 4; c++) acc[mi][ni][c] = 0.0f;

    // prologue: prefetch tile 0
    float4 ra0 = *(const float4*)(Ag);
    float4 ra1 = *(const float4*)(Ag + (size_t)64 * K);
    float4 rb0 = *(const float4*)(Bg);
    float4 rb1 = *(const float4*)(Bg + (size_t)64 * K);

    for (int k0 = 0; k0 < K; k0 += 16) {
        __syncthreads();   // previous compute done before overwrite
        As[(kc + 0) * LDT_ + r0]      = f2tf32(ra0.x);
        As[(kc + 1) * LDT_ + r0]      = f2tf32(ra0.y);
        As[(kc + 2) * LDT_ + r0]      = f2tf32(ra0.z);
        As[(kc + 3) * LDT_ + r0]      = f2tf32(ra0.w);
        As[(kc + 0) * LDT_ + r0 + 64] = f2tf32(ra1.x);
        As[(kc + 1) * LDT_ + r0 + 64] = f2tf32(ra1.y);
        As[(kc + 2) * LDT_ + r0 + 64] = f2tf32(ra1.z);
        As[(kc + 3) * LDT_ + r0 + 64] = f2tf32(ra1.w);
        Bs[(kc + 0) * LDT_ + r0]      = f2tf32(rb0.x);
        Bs[(kc + 1) * LDT_ + r0]      = f2tf32(rb0.y);
        Bs[(kc + 2) * LDT_ + r0]      = f2tf32(rb0.z);
        Bs[(kc + 3) * LDT_ + r0]      = f2tf32(rb0.w);
        Bs[(kc + 0) * LDT_ + r0 + 64] = f2tf32(rb1.x);
        Bs[(kc + 1) * LDT_ + r0 + 64] = f2tf32(rb1.y);
        Bs[(kc + 2) * LDT_ + r0 + 64] = f2tf32(rb1.z);
        Bs[(kc + 3) * LDT_ + r0 + 64] = f2tf32(rb1.w);
        __syncthreads();

        if (k0 + 16 < K) {   // prefetch next tile while computing
            ra0 = *(const float4*)(Ag + k0 + 16);
            ra1 = *(const float4*)(Ag + (size_t)64 * K + k0 + 16);
            rb0 = *(const float4*)(Bg + k0 + 16);
            rb1 = *(const float4*)(Bg + (size_t)64 * K + k0 + 16);
        }

#pragma unroll
        for (int kk = 0; kk < 2; kk++) {
            const int kb = kk * 8;
            uint32_t a[4][4];
#pragma unroll
            for (int mi = 0; mi < 4; mi++) {
                const int m0 = wm + mi * 16;
                a[mi][0] = As[(kb + tg) * LDT_ + m0 + g];
                a[mi][1] = As[(kb + tg) * LDT_ + m0 + g + 8];
                a[mi][2] = As[(kb + tg + 4) * LDT_ + m0 + g];
                a[mi][3] = As[(kb + tg + 4) * LDT_ + m0 + g + 8];
            }
            uint32_t bfr[4][2];
#pragma unroll
            for (int ni = 0; ni < 4; ni++) {
                const int n0 = wn + ni * 8;
                bfr[ni][0] = Bs[(kb + tg) * LDT_ + n0 + g];
                bfr[ni][1] = Bs[(kb + tg + 4) * LDT_ + n0 + g];
            }
#pragma unroll
            for (int mi = 0; mi < 4; mi++)
#pragma unroll
                for (int ni = 0; ni < 4; ni++) {
                    asm volatile(
                        "mma.sync.aligned.m16n8k8.row.col.f32.tf32.tf32.f32 "
                        "{%0,%1,%2,%3}, {%4,%5,%6,%7}, {%8,%9}, {%0,%1,%2,%3};\n"
                        : "+f"(acc[mi][ni][0]), "+f"(acc[mi][ni][1]),
                          "+f"(acc[mi][ni][2]), "+f"(acc[mi][ni][3])
                        : "r"(a[mi][0]), "r"(a[mi][1]), "r"(a[mi][2]), "r"(a[mi][3]),
                          "r"(bfr[ni][0]), "r"(bfr[ni][1]));
                }
        }
    }

    // epilogue: write C
#pragma unroll
    for (int mi = 0; mi < 4; mi++) {
        const int row = bm + wm + mi * 16 + g;
#pragma unroll
        for (int ni = 0; ni < 4; ni++) {
            const int col = bn + wn + ni * 8 + 2 * tg;
            float* cp0 = C + (size_t)row * N + col;
            float* cp1 = cp0 + (size_t)8 * N;
            *(float2*)cp0 = make_float2(acc[mi][ni][0], acc[mi][ni][1]);
            *(float2*)cp1 = make_float2(acc[mi][ni][2], acc[mi][ni][3]);
        }
    }
}

// ---------------- RoPE (in-place on g_q, g_k) -----------------------------
__global__ void rope_kernel(const float* __restrict__ cosp,
                            const float* __restrict__ sinp)
{
    int idx = blockIdx.x * blockDim.x + threadIdx.x;
    const int total = NTOK_ * (NH_ + NKV_) * (D_ / 2);
    if (idx >= total) return;

    int d    = idx % (D_ / 2);
    int rest = idx / (D_ / 2);
    int h    = rest % (NH_ + NKV_);
    int tok  = rest / (NH_ + NKV_);

    float c1 = cosp[(size_t)tok * D_ + d];
    float s1 = sinp[(size_t)tok * D_ + d];
    float c2 = cosp[(size_t)tok * D_ + d + D_ / 2];
    float s2 = sinp[(size_t)tok * D_ + d + D_ / 2];

    float* buf;
    if (h < NH_) buf = g_q + (size_t)tok * QDIM_ + h * D_;
    else         buf = g_k + (size_t)tok * KVDIM_ + (h - NH_) * D_;

    float x1 = buf[d];
    float x2 = buf[d + D_ / 2];
    buf[d]           = x1 * c1 - x2 * s1;
    buf[d + D_ / 2]  = x2 * c2 + x1 * s2;
}

// ---------------- block-sparse attention (fp32, unchanged) ----------------
#define ATTN_SMEM_FLOATS (64 * 128 + 64 * 128 + 64 * 65 + 3 * 64)
#define ATTN_SMEM_BYTES  (ATTN_SMEM_FLOATS * 4)

__global__ void __launch_bounds__(256)
attn_kernel()
{
    extern __shared__ float sm[];
    float* Qs   = sm;                       // 64*128
    float* KVs  = Qs + 64 * 128;            // 64*128 (K, then reused for V)
    float* Ss   = KVs + 64 * 128;           // 64*65 (padded)
    float* rowm = Ss + 64 * 65;             // 64
    float* rowl = rowm + 64;                // 64
    float* rowf = rowl + 64;                // 64
    __shared__ int sel_s[NSEL_];
    __shared__ int keep_s[NSEL_];

    const int qid = blockIdx.x;
    const int h   = blockIdx.y;
    const int b   = blockIdx.z;
    const int t   = threadIdx.x;
    const int kvh = h / (NH_ / NKV_);

    const float* qptr = g_q + ((size_t)(b * S_ + qid * BS_)) * QDIM_ + h * D_;
    for (int i = t; i < BS_ * D_; i += 256) {
        int r = i >> 7, d = i & 127;
        Qs[i] = qptr[(size_t)r * QDIM_ + d];
    }

    if (t < NSEL_) {
        int s;
        if (t < NGLOB_) { s = t * STRIDE_; if (s > KB_ - 1) s = KB_ - 1; }
        else            { int j = t - NGLOB_; s = qid - (NLOCAL_ - 1) + j;
                          s = s < 0 ? 0 : (s > KB_ - 1 ? KB_ - 1 : s); }
        bool valid = (s <= qid);
        bool dup = false;
        for (int jj = 0; jj < t; jj++) {
            int sj;
            if (jj < NGLOB_) { sj = jj * STRIDE_; if (sj > KB_ - 1) sj = KB_ - 1; }
            else             { int j2 = jj - NGLOB_; sj = qid - (NLOCAL_ - 1) + j2;
                               sj = sj < 0 ? 0 : (sj > KB_ - 1 ? KB_ - 1 : sj); }
            if (sj == s) dup = true;
        }
        sel_s[t]  = s;
        keep_s[t] = (valid && !dup) ? 1 : 0;
    }
    if (t < 64) { rowm[t] = -1e30f; rowl[t] = 0.0f; }

    float acc[32];
#pragma unroll
    for (int i = 0; i < 32; i++) acc[i] = 0.0f;

    const int tx = t & 15;
    const int ty = t >> 4;
    const int r0 = ty * 4;
    const int c0 = tx * 4;
    const int d0 = tx * 8;

    __syncthreads();

    for (int bi = 0; bi < NSEL_; bi++) {
        if (!keep_s[bi]) continue;
        const int kblk = sel_s[bi];
        const bool diag = (kblk == qid);

        const float* kptr = g_k + ((size_t)(b * S_ + kblk * BS_)) * KVDIM_ + kvh * D_;
        for (int i = t; i < BS_ * D_; i += 256) {
            int r = i >> 7, d = i & 127;
            KVs[i] = kptr[(size_t)r * KVDIM_ + d];
        }
        __syncthreads();

        float sc[4][4];
#pragma unroll
        for (int i = 0; i < 4; i++)
#pragma unroll
            for (int j = 0; j < 4; j++) sc[i][j] = 0.0f;

        for (int d = 0; d < D_; d += 4) {
            float4 qa[4], kb4[4];
#pragma unroll
            for (int i = 0; i < 4; i++) qa[i]  = *(const float4*)&Qs[(r0 + i) * D_ + d];
#pragma unroll
            for (int j = 0; j < 4; j++) kb4[j] = *(const float4*)&KVs[(c0 + j) * D_ + d];
#pragma unroll
            for (int i = 0; i < 4; i++)
#pragma unroll
                for (int j = 0; j < 4; j++)
                    sc[i][j] += qa[i].x * kb4[j].x + qa[i].y * kb4[j].y +
                                qa[i].z * kb4[j].z + qa[i].w * kb4[j].w;
        }
#pragma unroll
        for (int i = 0; i < 4; i++)
#pragma unroll
            for (int j = 0; j < 4; j++) {
                float v = sc[i][j] * SCALE_;
                if (diag && (c0 + j) > (r0 + i)) v += NEG_;
                Ss[(r0 + i) * 65 + (c0 + j)] = v;
            }
        __syncthreads();

        if (t < 64) {
            float m_old = rowm[t];
            float mx = m_old;
            for (int k = 0; k < 64; k++) mx = fmaxf(mx, Ss[t * 65 + k]);
            float f = __expf(m_old - mx);
            float sum = 0.0f;
            for (int k = 0; k < 64; k++) {
                float p = __expf(Ss[t * 65 + k] - mx);
                Ss[t * 65 + k] = p;
                sum += p;
            }
            rowl[t] = rowl[t] * f + sum;
            rowm[t] = mx;
            rowf[t] = f;
        }
        __syncthreads();

        float fr[4];
#pragma unroll
        for (int i = 0; i < 4; i++) fr[i] = rowf[r0 + i];
#pragma unroll
        for (int i = 0; i < 4; i++)
#pragma unroll
            for (int j = 0; j < 8; j++) acc[i * 8 + j] *= fr[i];

        const float* vptr = g_v + ((size_t)(b * S_ + kblk * BS_)) * KVDIM_ + kvh * D_;
        for (int i = t; i < BS_ * D_; i += 256) {
            int r = i >> 7, d = i & 127;
            KVs[i] = vptr[(size_t)r * KVDIM_ + d];
        }
        __syncthreads();

        for (int k = 0; k < 64; k++) {
            float p[4];
#pragma unroll
            for (int i = 0; i < 4; i++) p[i] = Ss[(r0 + i) * 65 + k];
            float4 v0 = *(const float4*)&KVs[k * D_ + d0];
            float4 v1 = *(const float4*)&KVs[k * D_ + d0 + 4];
#pragma unroll
            for (int i = 0; i < 4; i++) {
                acc[i * 8 + 0] += p[i] * v0.x;
                acc[i * 8 + 1] += p[i] * v0.y;
                acc[i * 8 + 2] += p[i] * v0.z;
                acc[i * 8 + 3] += p[i] * v0.w;
                acc[i * 8 + 4] += p[i] * v1.x;
                acc[i * 8 + 5] += p[i] * v1.y;
                acc[i * 8 + 6] += p[i] * v1.z;
                acc[i * 8 + 7] += p[i] * v1.w;
            }
        }
        __syncthreads();
    }

    float invl[4];
#pragma unroll
    for (int i = 0; i < 4; i++) invl[i] = 1.0f / rowl[r0 + i];
#pragma unroll
    for (int i = 0; i < 4; i++) {
        float* op = g_attn + ((size_t)(b * S_ + qid * BS_ + r0 + i)) * QDIM_ + h * D_ + d0;
        float4 o0 = make_float4(acc[i*8+0]*invl[i], acc[i*8+1]*invl[i],
                                acc[i*8+2]*invl[i], acc[i*8+3]*invl[i]);
        float4 o1 = make_float4(acc[i*8+4]*invl[i], acc[i*8+5]*invl[i],
                                acc[i*8+6]*invl[i], acc[i*8+7]*invl[i]);
        *(float4*)op       = o0;
        *(float4*)(op + 4) = o1;
    }
}

// ---------------- host launcher -------------------------------------------
extern "C" void kernel_launch(void* const* d_in, const int* in_sizes, int n_in,
                              void* d_out, int out_size)
{
    const float* X    = (const float*)d_in[0];
    const float* cosp = (const float*)d_in[1];
    const float* sinp = (const float*)d_in[2];
    const float* Wq   = (const float*)d_in[3];
    const float* Wk   = (const float*)d_in[4];
    const float* Wv   = (const float*)d_in[5];
    const float* Wo   = (const float*)d_in[6];
    float* out = (float*)d_out;

    float *qb, *kb, *vb, *ab;
    cudaGetSymbolAddress((void**)&qb, g_q);
    cudaGetSymbolAddress((void**)&kb, g_k);
    cudaGetSymbolAddress((void**)&vb, g_v);
    cudaGetSymbolAddress((void**)&ab, g_attn);

    cudaFuncSetAttribute(attn_kernel,
                         cudaFuncAttributeMaxDynamicSharedMemorySize,
                         ATTN_SMEM_BYTES);

    // QKV projections (tf32 tensor cores)
    gemm_tf32_nt<<<dim3(QDIM_ / 128, NTOK_ / 128), 256>>>(X, Wq, qb, NTOK_, QDIM_, H_);
    gemm_tf32_nt<<<dim3(KVDIM_ / 128, NTOK_ / 128), 256>>>(X, Wk, kb, NTOK_, KVDIM_, H_);
    gemm_tf32_nt<<<dim3(KVDIM_ / 128, NTOK_ / 128), 256>>>(X, Wv, vb, NTOK_, KVDIM_, H_);

    // RoPE on Q and K
    int rope_total = NTOK_ * (NH_ + NKV_) * (D_ / 2);
    rope_kernel<<<(rope_total + 255) / 256, 256>>>(cosp, sinp);

    // block-sparse attention
    attn_kernel<<<dim3(KB_, NH_, B_), 256, ATTN_SMEM_BYTES>>>();

    // output projection (tf32 tensor cores)
    gemm_tf32_nt<<<dim3(H_ / 128, NTOK_ / 128), 256>>>(ab, Wo, out, NTOK_, H_, QDIM_);
}

// round 3
// speedup vs baseline: 2.9866x; 1.9437x over previous
#include <cuda_runtime.h>
#include <cstdint>

// ---------------- problem constants ----------------
#define B_      2
#define S_      4096
#define H_      2048
#define NH_     16
#define NKV_    4
#define D_      128
#define BS_     64
#define KB_     (S_ / BS_)      // 64 key blocks
#define NGLOB_  4
#define NLOCAL_ 8
#define NSEL_   (NGLOB_ + NLOCAL_)   // 12
#define STRIDE_ 16
#define NTOK_   (B_ * S_)       // 8192
#define QDIM_   (NH_ * D_)      // 2048
#define KVDIM_  (NKV_ * D_)     // 512
#define SCALE_  0.088388347648318447f   // 1/sqrt(128)
#define NEG_    (-1000000000.0f)

// ---------------- scratch (static device globals; no runtime alloc) -------
__device__ float g_q[(size_t)NTOK_ * QDIM_];     // 64 MB
__device__ float g_k[(size_t)NTOK_ * KVDIM_];    // 16 MB
__device__ float g_v[(size_t)NTOK_ * KVDIM_];    // 16 MB
__device__ float g_attn[(size_t)NTOK_ * QDIM_];  // 64 MB

// ---------------- tf32 helpers --------------------------------------------
__device__ __forceinline__ uint32_t f2tf32(float x) {
    uint32_t u;
    asm("cvt.rna.tf32.f32 %0, %1;" : "=r"(u) : "f"(x));
    return u;
}
__device__ __forceinline__ void split_tf32(float x, uint32_t& hi, uint32_t& lo) {
    hi = f2tf32(x);
    lo = f2tf32(x - __uint_as_float(hi));
}
__device__ __forceinline__ void mma_tf32(float* c, const uint32_t* a, const uint32_t* b) {
    asm volatile(
        "mma.sync.aligned.m16n8k8.row.col.f32.tf32.tf32.f32 "
        "{%0,%1,%2,%3}, {%4,%5,%6,%7}, {%8,%9}, {%0,%1,%2,%3};\n"
        : "+f"(c[0]), "+f"(c[1]), "+f"(c[2]), "+f"(c[3])
        : "r"(a[0]), "r"(a[1]), "r"(a[2]), "r"(a[3]), "r"(b[0]), "r"(b[1]));
}

// ---------------- tf32 tensor-core GEMM (unchanged from R2) ---------------
#define LDT_ 132

__global__ void __launch_bounds__(256, 2)
gemm_tf32_nt(const float* __restrict__ A, const float* __restrict__ B,
             float* __restrict__ C, int M, int N, int K)
{
    __shared__ uint32_t As[16 * LDT_];
    __shared__ uint32_t Bs[16 * LDT_];

    const int bm = blockIdx.y * 128;
    const int bn = blockIdx.x * 128;
    const int t  = threadIdx.x;

    const int r0 = t >> 2;
    const int kc = (t & 3) << 2;
    const float* Ag = A + (size_t)(bm + r0) * K + kc;
    const float* Bg = B + (size_t)(bn + r0) * K + kc;

    const int lane = t & 31;
    const int warp = t >> 5;
    const int g  = lane >> 2;
    const int tg = lane & 3;
    const int wm = (warp >> 2) * 64;
    const int wn = (warp & 3) * 32;

    float acc[4][4][4];
#pragma unroll
    for (int mi = 0; mi < 4; mi++)
#pragma unroll
        for (int ni = 0; ni < 4; ni++)
#pragma unroll
            for (int c = 0; c < 4; c++) acc[mi][ni][c] = 0.0f;

    float4 ra0 = *(const float4*)(Ag);
    float4 ra1 = *(const float4*)(Ag + (size_t)64 * K);
    float4 rb0 = *(const float4*)(Bg);
    float4 rb1 = *(const float4*)(Bg + (size_t)64 * K);

    for (int k0 = 0; k0 < K; k0 += 16) {
        __syncthreads();
        As[(kc + 0) * LDT_ + r0]      = f2tf32(ra0.x);
        As[(kc + 1) * LDT_ + r0]      = f2tf32(ra0.y);
        As[(kc + 2) * LDT_ + r0]      = f2tf32(ra0.z);
        As[(kc + 3) * LDT_ + r0]      = f2tf32(ra0.w);
        As[(kc + 0) * LDT_ + r0 + 64] = f2tf32(ra1.x);
        As[(kc + 1) * LDT_ + r0 + 64] = f2tf32(ra1.y);
        As[(kc + 2) * LDT_ + r0 + 64] = f2tf32(ra1.z);
        As[(kc + 3) * LDT_ + r0 + 64] = f2tf32(ra1.w);
        Bs[(kc + 0) * LDT_ + r0]      = f2tf32(rb0.x);
        Bs[(kc + 1) * LDT_ + r0]      = f2tf32(rb0.y);
        Bs[(kc + 2) * LDT_ + r0]      = f2tf32(rb0.z);
        Bs[(kc + 3) * LDT_ + r0]      = f2tf32(rb0.w);
        Bs[(kc + 0) * LDT_ + r0 + 64] = f2tf32(rb1.x);
        Bs[(kc + 1) * LDT_ + r0 + 64] = f2tf32(rb1.y);
        Bs[(kc + 2) * LDT_ + r0 + 64] = f2tf32(rb1.z);
        Bs[(kc + 3) * LDT_ + r0 + 64] = f2tf32(rb1.w);
        __syncthreads();

        if (k0 + 16 < K) {
            ra0 = *(const float4*)(Ag + k0 + 16);
            ra1 = *(const float4*)(Ag + (size_t)64 * K + k0 + 16);
            rb0 = *(const float4*)(Bg + k0 + 16);
            rb1 = *(const float4*)(Bg + (size_t)64 * K + k0 + 16);
        }

#pragma unroll
        for (int kk = 0; kk < 2; kk++) {
            const int kb = kk * 8;
            uint32_t a[4][4];
#pragma unroll
            for (int mi = 0; mi < 4; mi++) {
                const int m0 = wm + mi * 16;
                a[mi][0] = As[(kb + tg) * LDT_ + m0 + g];
                a[mi][1] = As[(kb + tg) * LDT_ + m0 + g + 8];
                a[mi][2] = As[(kb + tg + 4) * LDT_ + m0 + g];
                a[mi][3] = As[(kb + tg + 4) * LDT_ + m0 + g + 8];
            }
            uint32_t bfr[4][2];
#pragma unroll
            for (int ni = 0; ni < 4; ni++) {
                const int n0 = wn + ni * 8;
                bfr[ni][0] = Bs[(kb + tg) * LDT_ + n0 + g];
                bfr[ni][1] = Bs[(kb + tg + 4) * LDT_ + n0 + g];
            }
#pragma unroll
            for (int mi = 0; mi < 4; mi++)
#pragma unroll
                for (int ni = 0; ni < 4; ni++)
                    mma_tf32(acc[mi][ni], a[mi], bfr[ni]);
        }
    }

#pragma unroll
    for (int mi = 0; mi < 4; mi++) {
        const int row = bm + wm + mi * 16 + g;
#pragma unroll
        for (int ni = 0; ni < 4; ni++) {
            const int col = bn + wn + ni * 8 + 2 * tg;
            float* cp0 = C + (size_t)row * N + col;
            float* cp1 = cp0 + (size_t)8 * N;
            *(float2*)cp0 = make_float2(acc[mi][ni][0], acc[mi][ni][1]);
            *(float2*)cp1 = make_float2(acc[mi][ni][2], acc[mi][ni][3]);
        }
    }
}

// ---------------- RoPE (in-place on g_q, g_k) -----------------------------
__global__ void rope_kernel(const float* __restrict__ cosp,
                            const float* __restrict__ sinp)
{
    int idx = blockIdx.x * blockDim.x + threadIdx.x;
    const int total = NTOK_ * (NH_ + NKV_) * (D_ / 2);
    if (idx >= total) return;

    int d    = idx % (D_ / 2);
    int rest = idx / (D_ / 2);
    int h    = rest % (NH_ + NKV_);
    int tok  = rest / (NH_ + NKV_);

    float c1 = cosp[(size_t)tok * D_ + d];
    float s1 = sinp[(size_t)tok * D_ + d];
    float c2 = cosp[(size_t)tok * D_ + d + D_ / 2];
    float s2 = sinp[(size_t)tok * D_ + d + D_ / 2];

    float* buf;
    if (h < NH_) buf = g_q + (size_t)tok * QDIM_ + h * D_;
    else         buf = g_k + (size_t)tok * KVDIM_ + (h - NH_) * D_;

    float x1 = buf[d];
    float x2 = buf[d + D_ / 2];
    buf[d]           = x1 * c1 - x2 * s1;
    buf[d + D_ / 2]  = x2 * c2 + x1 * s2;
}

// ---------------- block-sparse attention, tensor-core version -------------
// grid (qblock, head, batch), 256 threads = 8 warps.
// Warp layout: wm=(warp>>1)*16 (m-strip), nh=warp&1 (n-half).
// S = Q@K^T (m64 n64 k128) then PV (m64 n128 k64), both 3xTF32 mma.
#define LDQ_   132   // Qs / KVs row stride (floats)
#define LDSS_  68    // Ss row stride
#define AT_SMEM_FLOATS (64*LDQ_ + 64*LDQ_ + 64*LDSS_ + 128 + 128 + 3*64)
#define AT_SMEM_BYTES  (AT_SMEM_FLOATS * 4)

__global__ void __launch_bounds__(256, 2)
attn_kernel()
{
    extern __shared__ float sm[];
    float* Qs   = sm;                   // [64][132]
    float* KVs  = Qs + 64 * LDQ_;       // [64][132]  K then V
    float* Ss   = KVs + 64 * LDQ_;      // [64][68]   P (probabilities)
    float* wmax = Ss + 64 * LDSS_;      // [2][64]
    float* wsum = wmax + 128;           // [2][64]
    float* rowm = wsum + 128;           // [64]
    float* rowl = rowm + 64;            // [64]
    float* rowf = rowl + 64;            // [64]
    __shared__ int sel_s[NSEL_];
    __shared__ int keep_s[NSEL_];

    const int qid = blockIdx.x;
    const int h   = blockIdx.y;
    const int b   = blockIdx.z;
    const int t   = threadIdx.x;
    const int kvh = h / (NH_ / NKV_);

    const int warp = t >> 5, lane = t & 31;
    const int g  = lane >> 2;       // 0..7
    const int tg = lane & 3;        // 0..3
    const int wm  = (warp >> 1) * 16;   // m strip
    const int nh  = warp & 1;           // n half
    const int wn  = nh * 32;            // S col base
    const int wn2 = nh * 64;            // PV col base
    const int row0 = wm + g;            // this thread's two rows
    const int row1 = wm + g + 8;

    // load Q block (fp32) [64][128] -> Qs
    const float* qptr = g_q + ((size_t)(b * S_ + qid * BS_)) * QDIM_ + h * D_;
    for (int i4 = t; i4 < 64 * 32; i4 += 256) {
        int r = i4 >> 5, d4 = (i4 & 31) << 2;
        *(float4*)&Qs[r * LDQ_ + d4] = *(const float4*)(qptr + (size_t)r * QDIM_ + d4);
    }

    // block selection + dedup
    if (t < NSEL_) {
        int s;
        if (t < NGLOB_) { s = t * STRIDE_; if (s > KB_ - 1) s = KB_ - 1; }
        else            { int j = t - NGLOB_; s = qid - (NLOCAL_ - 1) + j;
                          s = s < 0 ? 0 : (s > KB_ - 1 ? KB_ - 1 : s); }
        bool valid = (s <= qid);
        bool dup = false;
        for (int jj = 0; jj < t; jj++) {
            int sj;
            if (jj < NGLOB_) { sj = jj * STRIDE_; if (sj > KB_ - 1) sj = KB_ - 1; }
            else             { int j2 = jj - NGLOB_; sj = qid - (NLOCAL_ - 1) + j2;
                               sj = sj < 0 ? 0 : (sj > KB_ - 1 ? KB_ - 1 : sj); }
            if (sj == s) dup = true;
        }
        sel_s[t]  = s;
        keep_s[t] = (valid && !dup) ? 1 : 0;
    }
    if (t < 64) { rowm[t] = -1e30f; rowl[t] = 0.0f; }

    float o[8][4];
#pragma unroll
    for (int ni = 0; ni < 8; ni++)
#pragma unroll
        for (int c = 0; c < 4; c++) o[ni][c] = 0.0f;

    __syncthreads();

    for (int bi = 0; bi < NSEL_; bi++) {
        if (!keep_s[bi]) continue;
        const int kblk = sel_s[bi];
        const bool diag = (kblk == qid);

        // ---- load K block -> KVs
        const float* kptr = g_k + ((size_t)(b * S_ + kblk * BS_)) * KVDIM_ + kvh * D_;
        for (int i4 = t; i4 < 64 * 32; i4 += 256) {
            int r = i4 >> 5, d4 = (i4 & 31) << 2;
            *(float4*)&KVs[r * LDQ_ + d4] = *(const float4*)(kptr + (size_t)r * KVDIM_ + d4);
        }
        __syncthreads();

        // ---- S = Q @ K^T (3xTF32), warp tile m16 x n32
        float sacc[4][4];
#pragma unroll
        for (int ni = 0; ni < 4; ni++)
#pragma unroll
            for (int c = 0; c < 4; c++) sacc[ni][c] = 0.0f;

#pragma unroll
        for (int ks = 0; ks < 16; ks++) {
            const int kb = ks * 8;
            uint32_t ahi[4], alo[4];
            split_tf32(Qs[row0 * LDQ_ + kb + tg],     ahi[0], alo[0]);
            split_tf32(Qs[row1 * LDQ_ + kb + tg],     ahi[1], alo[1]);
            split_tf32(Qs[row0 * LDQ_ + kb + tg + 4], ahi[2], alo[2]);
            split_tf32(Qs[row1 * LDQ_ + kb + tg + 4], ahi[3], alo[3]);
#pragma unroll
            for (int ni = 0; ni < 4; ni++) {
                const int n = wn + ni * 8 + g;
                uint32_t bhi[2], blo[2];
                split_tf32(KVs[n * LDQ_ + kb + tg],     bhi[0], blo[0]);
                split_tf32(KVs[n * LDQ_ + kb + tg + 4], bhi[1], blo[1]);
                mma_tf32(sacc[ni], ahi, bhi);
                mma_tf32(sacc[ni], ahi, blo);
                mma_tf32(sacc[ni], alo, bhi);
            }
        }

        // ---- scale + causal mask + row partial max (registers)
        float pm0 = -1e30f, pm1 = -1e30f;
#pragma unroll
        for (int ni = 0; ni < 4; ni++) {
            const int colb = wn + ni * 8 + 2 * tg;
#pragma unroll
            for (int c = 0; c < 4; c++) {
                const int col = colb + (c & 1);
                const int row = (c < 2) ? row0 : row1;
                float v = sacc[ni][c] * SCALE_;
                if (diag && col > row) v += NEG_;
                sacc[ni][c] = v;
                if (c < 2) pm0 = fmaxf(pm0, v);
                else       pm1 = fmaxf(pm1, v);
            }
        }
        pm0 = fmaxf(pm0, __shfl_xor_sync(0xffffffff, pm0, 1));
        pm0 = fmaxf(pm0, __shfl_xor_sync(0xffffffff, pm0, 2));
        pm1 = fmaxf(pm1, __shfl_xor_sync(0xffffffff, pm1, 1));
        pm1 = fmaxf(pm1, __shfl_xor_sync(0xffffffff, pm1, 2));
        if (tg == 0) {
            wmax[nh * 64 + row0] = pm0;
            wmax[nh * 64 + row1] = pm1;
        }
        __syncthreads();

        // ---- full row max; exp; partial sums
        float mx0 = fmaxf(fmaxf(wmax[row0], wmax[64 + row0]), rowm[row0]);
        float mx1 = fmaxf(fmaxf(wmax[row1], wmax[64 + row1]), rowm[row1]);
        float ps0 = 0.0f, ps1 = 0.0f;
#pragma unroll
        for (int ni = 0; ni < 4; ni++) {
#pragma unroll
            for (int c = 0; c < 4; c++) {
                float p = __expf(sacc[ni][c] - ((c < 2) ? mx0 : mx1));
                sacc[ni][c] = p;
                if (c < 2) ps0 += p; else ps1 += p;
            }
        }
        ps0 += __shfl_xor_sync(0xffffffff, ps0, 1);
        ps0 += __shfl_xor_sync(0xffffffff, ps0, 2);
        ps1 += __shfl_xor_sync(0xffffffff, ps1, 1);
        ps1 += __shfl_xor_sync(0xffffffff, ps1, 2);
        if (tg == 0) {
            wsum[nh * 64 + row0] = ps0;
            wsum[nh * 64 + row1] = ps1;
        }
        float mxt = 0.0f, ft = 0.0f;
        if (t < 64) {
            mxt = fmaxf(fmaxf(wmax[t], wmax[64 + t]), rowm[t]);
            ft  = __expf(rowm[t] - mxt);
            rowf[t] = ft;
        }
        __syncthreads();

        if (t < 64) {
            rowl[t] = rowl[t] * ft + wsum[t] + wsum[64 + t];
            rowm[t] = mxt;
        }

        // ---- rescale O; store P to Ss; load V
        {
            float f0 = rowf[row0], f1 = rowf[row1];
#pragma unroll
            for (int ni = 0; ni < 8; ni++) {
                o[ni][0] *= f0; o[ni][1] *= f0;
                o[ni][2] *= f1; o[ni][3] *= f1;
            }
        }
#pragma unroll
        for (int ni = 0; ni < 4; ni++) {
            const int colb = wn + ni * 8 + 2 * tg;
            *(float2*)&Ss[row0 * LDSS_ + colb] = make_float2(sacc[ni][0], sacc[ni][1]);
            *(float2*)&Ss[row1 * LDSS_ + colb] = make_float2(sacc[ni][2], sacc[ni][3]);
        }
        const float* vptr = g_v + ((size_t)(b * S_ + kblk * BS_)) * KVDIM_ + kvh * D_;
        for (int i4 = t; i4 < 64 * 32; i4 += 256) {
            int r = i4 >> 5, d4 = (i4 & 31) << 2;
            *(float4*)&KVs[r * LDQ_ + d4] = *(const float4*)(vptr + (size_t)r * KVDIM_ + d4);
        }
        __syncthreads();

        // ---- O += P @ V (3xTF32), warp tile m16 x n64
#pragma unroll
        for (int ks = 0; ks < 8; ks++) {
            const int kb = ks * 8;
            uint32_t ahi[4], alo[4];
            split_tf32(Ss[row0 * LDSS_ + kb + tg],     ahi[0], alo[0]);
            split_tf32(Ss[row1 * LDSS_ + kb + tg],     ahi[1], alo[1]);
            split_tf32(Ss[row0 * LDSS_ + kb + tg + 4], ahi[2], alo[2]);
            split_tf32(Ss[row1 * LDSS_ + kb + tg + 4], ahi[3], alo[3]);
#pragma unroll
            for (int ni = 0; ni < 8; ni++) {
                const int n = wn2 + ni * 8 + g;
                uint32_t bhi[2], blo[2];
                split_tf32(KVs[(kb + tg) * LDQ_ + n],     bhi[0], blo[0]);
                split_tf32(KVs[(kb + tg + 4) * LDQ_ + n], bhi[1], blo[1]);
                mma_tf32(o[ni], ahi, bhi);
                mma_tf32(o[ni], ahi, blo);
                mma_tf32(o[ni], alo, bhi);
            }
        }
        __syncthreads();   // KVs/Ss consumed; safe for next iteration
    }

    // ---- finalize: divide by softmax denom, write out
    const float invl0 = 1.0f / rowl[row0];
    const float invl1 = 1.0f / rowl[row1];
    float* ob0 = g_attn + ((size_t)(b * S_ + qid * BS_ + row0)) * QDIM_ + h * D_;
    float* ob1 = g_attn + ((size_t)(b * S_ + qid * BS_ + row1)) * QDIM_ + h * D_;
#pragma unroll
    for (int ni = 0; ni < 8; ni++) {
        const int col = wn2 + ni * 8 + 2 * tg;
        *(float2*)(ob0 + col) = make_float2(o[ni][0] * invl0, o[ni][1] * invl0);
        *(float2*)(ob1 + col) = make_float2(o[ni][2] * invl1, o[ni][3] * invl1);
    }
}

// ---------------- host launcher -------------------------------------------
extern "C" void kernel_launch(void* const* d_in, const int* in_sizes, int n_in,
                              void* d_out, int out_size)
{
    const float* X    = (const float*)d_in[0];
    const float* cosp = (const float*)d_in[1];
    const float* sinp = (const float*)d_in[2];
    const float* Wq   = (const float*)d_in[3];
    const float* Wk   = (const float*)d_in[4];
    const float* Wv   = (const float*)d_in[5];
    const float* Wo   = (const float*)d_in[6];
    float* out = (float*)d_out;

    float *qb, *kb, *vb, *ab;
    cudaGetSymbolAddress((void**)&qb, g_q);
    cudaGetSymbolAddress((void**)&kb, g_k);
    cudaGetSymbolAddress((void**)&vb, g_v);
    cudaGetSymbolAddress((void**)&ab, g_attn);

    cudaFuncSetAttribute(attn_kernel,
                         cudaFuncAttributeMaxDynamicSharedMemorySize,
                         AT_SMEM_BYTES);

    // QKV projections (tf32 tensor cores)
    gemm_tf32_nt<<<dim3(QDIM_ / 128, NTOK_ / 128), 256>>>(X, Wq, qb, NTOK_, QDIM_, H_);
    gemm_tf32_nt<<<dim3(KVDIM_ / 128, NTOK_ / 128), 256>>>(X, Wk, kb, NTOK_, KVDIM_, H_);
    gemm_tf32_nt<<<dim3(KVDIM_ / 128, NTOK_ / 128), 256>>>(X, Wv, vb, NTOK_, KVDIM_, H_);

    // RoPE on Q and K
    int rope_total = NTOK_ * (NH_ + NKV_) * (D_ / 2);
    rope_kernel<<<(rope_total + 255) / 256, 256>>>(cosp, sinp);

    // block-sparse attention (tensor cores, 3xTF32)
    attn_kernel<<<dim3(KB_, NH_, B_), 256, AT_SMEM_BYTES>>>();

    // output projection (tf32 tensor cores)
    gemm_tf32_nt<<<dim3(H_ / 128, NTOK_ / 128), 256>>>(ab, Wo, out, NTOK_, H_, QDIM_);
}

// round 4
// speedup vs baseline: 3.5509x; 1.1890x over previous
#include <cuda_runtime.h>
#include <cstdint>

// ---------------- problem constants ----------------
#define B_      2
#define S_      4096
#define H_      2048
#define NH_     16
#define NKV_    4
#define D_      128
#define BS_     64
#define KB_     (S_ / BS_)      // 64 key blocks
#define NGLOB_  4
#define NLOCAL_ 8
#define NSEL_   (NGLOB_ + NLOCAL_)   // 12
#define STRIDE_ 16
#define NTOK_   (B_ * S_)       // 8192
#define QDIM_   (NH_ * D_)      // 2048
#define KVDIM_  (NKV_ * D_)     // 512
#define SCALE_  0.088388347648318447f   // 1/sqrt(128)
#define NEG_    (-1000000000.0f)

// ---------------- scratch (static device globals; no runtime alloc) -------
__device__ float    g_q[(size_t)NTOK_ * QDIM_];     // 64 MB
__device__ float    g_k[(size_t)NTOK_ * KVDIM_];    // 16 MB
__device__ float    g_v[(size_t)NTOK_ * KVDIM_];    // 16 MB
__device__ float    g_attn[(size_t)NTOK_ * QDIM_];  // 64 MB (tf32 bits)
__device__ uint32_t g_xt[(size_t)NTOK_ * H_];       // 64 MB (X in tf32)
__device__ uint32_t g_wt[(size_t)QDIM_ * H_];       // 16 MB (weights in tf32)

// ---------------- tf32 helpers --------------------------------------------
__device__ __forceinline__ uint32_t f2tf32(float x) {
    uint32_t u;
    asm("cvt.rna.tf32.f32 %0, %1;" : "=r"(u) : "f"(x));
    return u;
}
__device__ __forceinline__ void split_tf32(float x, uint32_t& hi, uint32_t& lo) {
    hi = f2tf32(x);
    lo = f2tf32(x - __uint_as_float(hi));
}
__device__ __forceinline__ void mma_tf32(float* c, const uint32_t* a, const uint32_t* b) {
    asm volatile(
        "mma.sync.aligned.m16n8k8.row.col.f32.tf32.tf32.f32 "
        "{%0,%1,%2,%3}, {%4,%5,%6,%7}, {%8,%9}, {%0,%1,%2,%3};\n"
        : "+f"(c[0]), "+f"(c[1]), "+f"(c[2]), "+f"(c[3])
        : "r"(a[0]), "r"(a[1]), "r"(a[2]), "r"(a[3]), "r"(b[0]), "r"(b[1]));
}
__device__ __forceinline__ void cp_async16(uint32_t saddr, const void* gptr) {
    asm volatile("cp.async.cg.shared.global [%0], [%1], 16;\n"
                 :: "r"(saddr), "l"(gptr));
}

// ---------------- fp32 -> tf32 conversion kernel --------------------------
__global__ void cvt_tf32_kernel(const float* __restrict__ in,
                                uint32_t* __restrict__ out, int n4)
{
    int i = blockIdx.x * blockDim.x + threadIdx.x;
    if (i >= n4) return;
    float4 v = ((const float4*)in)[i];
    uint4 o;
    o.x = f2tf32(v.x); o.y = f2tf32(v.y);
    o.z = f2tf32(v.z); o.w = f2tf32(v.w);
    ((uint4*)out)[i] = o;
}

// ---------------- pipelined tf32 GEMM -------------------------------------
//  C[M,N] = A[M,K] @ B[N,K]^T ; A,B already tf32 bits, row-major, K contig.
//  128x128 CTA tile, BK=16, 3-stage cp.async pipeline, 256 threads,
//  8 warps 2x4, warp tile 64x32 (4x4 m16n8k8).
#define BKG_  16
#define LDAG_ 20     // floats per smem row (16 + 4 pad) -> conflict-free frags
#define STG_  3
#define GEMM_SMEM_BYTES (STG_ * 2 * 128 * LDAG_ * 4)   // 61440

struct Frag { float a[4][4][4]; };

__global__ void __launch_bounds__(256, 2)
gemm_tf32_pipe(const uint32_t* __restrict__ A, const uint32_t* __restrict__ B,
               float* __restrict__ C, int M, int N, int K)
{
    extern __shared__ uint32_t smg[];
    uint32_t* As = smg;                          // [STG_][128*LDAG_]
    uint32_t* Bs = smg + STG_ * 128 * LDAG_;

    const int bm = blockIdx.y * 128;
    const int bn = blockIdx.x * 128;
    const int t  = threadIdx.x;
    const int lane = t & 31, warp = t >> 5;
    const int g  = lane >> 2, tg = lane & 3;
    const int wm = (warp >> 2) * 64;
    const int wn = (warp & 3) * 32;

    float acc[4][4][4];
#pragma unroll
    for (int mi = 0; mi < 4; mi++)
#pragma unroll
        for (int ni = 0; ni < 4; ni++)
#pragma unroll
            for (int c = 0; c < 4; c++) acc[mi][ni][c] = 0.0f;

    // chunk mapping: 512 16B-chunks per matrix per stage; 2 per thread.
    auto load_stage = [&](int s, int k0) {
#pragma unroll
        for (int i = 0; i < 2; i++) {
            int c   = t + i * 256;
            int row = c >> 2;
            int kc  = (c & 3) << 2;
            uint32_t sa = (uint32_t)__cvta_generic_to_shared(
                &As[s * 128 * LDAG_ + row * LDAG_ + kc]);
            cp_async16(sa, A + (size_t)(bm + row) * K + k0 + kc);
            uint32_t sb = (uint32_t)__cvta_generic_to_shared(
                &Bs[s * 128 * LDAG_ + row * LDAG_ + kc]);
            cp_async16(sb, B + (size_t)(bn + row) * K + k0 + kc);
        }
        asm volatile("cp.async.commit_group;\n");
    };

    auto compute_stage = [&](int s) {
        const uint32_t* as = As + s * 128 * LDAG_;
        const uint32_t* bs = Bs + s * 128 * LDAG_;
#pragma unroll
        for (int kk = 0; kk < 2; kk++) {
            const int kb = kk * 8;
            uint32_t a[4][4];
#pragma unroll
            for (int mi = 0; mi < 4; mi++) {
                const int m0 = wm + mi * 16;
                a[mi][0] = as[(m0 + g) * LDAG_ + kb + tg];
                a[mi][1] = as[(m0 + g + 8) * LDAG_ + kb + tg];
                a[mi][2] = as[(m0 + g) * LDAG_ + kb + tg + 4];
                a[mi][3] = as[(m0 + g + 8) * LDAG_ + kb + tg + 4];
            }
            uint32_t bf[4][2];
#pragma unroll
            for (int ni = 0; ni < 4; ni++) {
                const int n0 = wn + ni * 8;
                bf[ni][0] = bs[(n0 + g) * LDAG_ + kb + tg];
                bf[ni][1] = bs[(n0 + g) * LDAG_ + kb + tg + 4];
            }
#pragma unroll
            for (int mi = 0; mi < 4; mi++)
#pragma unroll
                for (int ni = 0; ni < 4; ni++)
                    mma_tf32(acc[mi][ni], a[mi], bf[ni]);
        }
    };

    const int niter = K / BKG_;
    load_stage(0, 0);
    load_stage(1, BKG_);

    for (int i = 0; i < niter - 1; i++) {
        asm volatile("cp.async.wait_group 1;\n");
        __syncthreads();
        if (i + 2 < niter) load_stage((i + 2) % STG_, (i + 2) * BKG_);
        compute_stage(i % STG_);
    }
    asm volatile("cp.async.wait_group 0;\n");
    __syncthreads();
    compute_stage((niter - 1) % STG_);

    // epilogue
#pragma unroll
    for (int mi = 0; mi < 4; mi++) {
        const int row = bm + wm + mi * 16 + g;
#pragma unroll
        for (int ni = 0; ni < 4; ni++) {
            const int col = bn + wn + ni * 8 + 2 * tg;
            float* cp0 = C + (size_t)row * N + col;
            float* cp1 = cp0 + (size_t)8 * N;
            *(float2*)cp0 = make_float2(acc[mi][ni][0], acc[mi][ni][1]);
            *(float2*)cp1 = make_float2(acc[mi][ni][2], acc[mi][ni][3]);
        }
    }
}

// ---------------- RoPE (in-place on g_q, g_k) -----------------------------
__global__ void rope_kernel(const float* __restrict__ cosp,
                            const float* __restrict__ sinp)
{
    int idx = blockIdx.x * blockDim.x + threadIdx.x;
    const int total = NTOK_ * (NH_ + NKV_) * (D_ / 2);
    if (idx >= total) return;

    int d    = idx % (D_ / 2);
    int rest = idx / (D_ / 2);
    int h    = rest % (NH_ + NKV_);
    int tok  = rest / (NH_ + NKV_);

    float c1 = cosp[(size_t)tok * D_ + d];
    float s1 = sinp[(size_t)tok * D_ + d];
    float c2 = cosp[(size_t)tok * D_ + d + D_ / 2];
    float s2 = sinp[(size_t)tok * D_ + d + D_ / 2];

    float* buf;
    if (h < NH_) buf = g_q + (size_t)tok * QDIM_ + h * D_;
    else         buf = g_k + (size_t)tok * KVDIM_ + (h - NH_) * D_;

    float x1 = buf[d];
    float x2 = buf[d + D_ / 2];
    buf[d]           = x1 * c1 - x2 * s1;
    buf[d + D_ / 2]  = x2 * c2 + x1 * s2;
}

// ---------------- block-sparse attention (tensor cores, 3xTF32) -----------
#define LDQ_   132
#define LDSS_  68
#define AT_SMEM_FLOATS (64*LDQ_ + 64*LDQ_ + 64*LDSS_ + 128 + 128 + 3*64)
#define AT_SMEM_BYTES  (AT_SMEM_FLOATS * 4)

__global__ void __launch_bounds__(256, 2)
attn_kernel()
{
    extern __shared__ float sm[];
    float* Qs   = sm;                   // [64][132]
    float* KVs  = Qs + 64 * LDQ_;       // [64][132]
    float* Ss   = KVs + 64 * LDQ_;      // [64][68]
    float* wmax = Ss + 64 * LDSS_;      // [2][64]
    float* wsum = wmax + 128;           // [2][64]
    float* rowm = wsum + 128;           // [64]
    float* rowl = rowm + 64;            // [64]
    float* rowf = rowl + 64;            // [64]
    __shared__ int sel_s[NSEL_];
    __shared__ int keep_s[NSEL_];

    const int qid = blockIdx.x;
    const int h   = blockIdx.y;
    const int b   = blockIdx.z;
    const int t   = threadIdx.x;
    const int kvh = h / (NH_ / NKV_);

    const int warp = t >> 5, lane = t & 31;
    const int g  = lane >> 2;
    const int tg = lane & 3;
    const int wm  = (warp >> 1) * 16;
    const int nh  = warp & 1;
    const int wn  = nh * 32;
    const int wn2 = nh * 64;
    const int row0 = wm + g;
    const int row1 = wm + g + 8;

    const float* qptr = g_q + ((size_t)(b * S_ + qid * BS_)) * QDIM_ + h * D_;
    for (int i4 = t; i4 < 64 * 32; i4 += 256) {
        int r = i4 >> 5, d4 = (i4 & 31) << 2;
        *(float4*)&Qs[r * LDQ_ + d4] = *(const float4*)(qptr + (size_t)r * QDIM_ + d4);
    }

    if (t < NSEL_) {
        int s;
        if (t < NGLOB_) { s = t * STRIDE_; if (s > KB_ - 1) s = KB_ - 1; }
        else            { int j = t - NGLOB_; s = qid - (NLOCAL_ - 1) + j;
                          s = s < 0 ? 0 : (s > KB_ - 1 ? KB_ - 1 : s); }
        bool valid = (s <= qid);
        bool dup = false;
        for (int jj = 0; jj < t; jj++) {
            int sj;
            if (jj < NGLOB_) { sj = jj * STRIDE_; if (sj > KB_ - 1) sj = KB_ - 1; }
            else             { int j2 = jj - NGLOB_; sj = qid - (NLOCAL_ - 1) + j2;
                               sj = sj < 0 ? 0 : (sj > KB_ - 1 ? KB_ - 1 : sj); }
            if (sj == s) dup = true;
        }
        sel_s[t]  = s;
        keep_s[t] = (valid && !dup) ? 1 : 0;
    }
    if (t < 64) { rowm[t] = -1e30f; rowl[t] = 0.0f; }

    float o[8][4];
#pragma unroll
    for (int ni = 0; ni < 8; ni++)
#pragma unroll
        for (int c = 0; c < 4; c++) o[ni][c] = 0.0f;

    __syncthreads();

    for (int bi = 0; bi < NSEL_; bi++) {
        if (!keep_s[bi]) continue;
        const int kblk = sel_s[bi];
        const bool diag = (kblk == qid);

        const float* kptr = g_k + ((size_t)(b * S_ + kblk * BS_)) * KVDIM_ + kvh * D_;
        for (int i4 = t; i4 < 64 * 32; i4 += 256) {
            int r = i4 >> 5, d4 = (i4 & 31) << 2;
            *(float4*)&KVs[r * LDQ_ + d4] = *(const float4*)(kptr + (size_t)r * KVDIM_ + d4);
        }
        __syncthreads();

        float sacc[4][4];
#pragma unroll
        for (int ni = 0; ni < 4; ni++)
#pragma unroll
            for (int c = 0; c < 4; c++) sacc[ni][c] = 0.0f;

#pragma unroll
        for (int ks = 0; ks < 16; ks++) {
            const int kb = ks * 8;
            uint32_t ahi[4], alo[4];
            split_tf32(Qs[row0 * LDQ_ + kb + tg],     ahi[0], alo[0]);
            split_tf32(Qs[row1 * LDQ_ + kb + tg],     ahi[1], alo[1]);
            split_tf32(Qs[row0 * LDQ_ + kb + tg + 4], ahi[2], alo[2]);
            split_tf32(Qs[row1 * LDQ_ + kb + tg + 4], ahi[3], alo[3]);
#pragma unroll
            for (int ni = 0; ni < 4; ni++) {
                const int n = wn + ni * 8 + g;
                uint32_t bhi[2], blo[2];
                split_tf32(KVs[n * LDQ_ + kb + tg],     bhi[0], blo[0]);
                split_tf32(KVs[n * LDQ_ + kb + tg + 4], bhi[1], blo[1]);
                mma_tf32(sacc[ni], ahi, bhi);
                mma_tf32(sacc[ni], ahi, blo);
                mma_tf32(sacc[ni], alo, bhi);
            }
        }

        float pm0 = -1e30f, pm1 = -1e30f;
#pragma unroll
        for (int ni = 0; ni < 4; ni++) {
            const int colb = wn + ni * 8 + 2 * tg;
#pragma unroll
            for (int c = 0; c < 4; c++) {
                const int col = colb + (c & 1);
                const int row = (c < 2) ? row0 : row1;
                float v = sacc[ni][c] * SCALE_;
                if (diag && col > row) v += NEG_;
                sacc[ni][c] = v;
                if (c < 2) pm0 = fmaxf(pm0, v);
                else       pm1 = fmaxf(pm1, v);
            }
        }
        pm0 = fmaxf(pm0, __shfl_xor_sync(0xffffffff, pm0, 1));
        pm0 = fmaxf(pm0, __shfl_xor_sync(0xffffffff, pm0, 2));
        pm1 = fmaxf(pm1, __shfl_xor_sync(0xffffffff, pm1, 1));
        pm1 = fmaxf(pm1, __shfl_xor_sync(0xffffffff, pm1, 2));
        if (tg == 0) {
            wmax[nh * 64 + row0] = pm0;
            wmax[nh * 64 + row1] = pm1;
        }
        __syncthreads();

        float mx0 = fmaxf(fmaxf(wmax[row0], wmax[64 + row0]), rowm[row0]);
        float mx1 = fmaxf(fmaxf(wmax[row1], wmax[64 + row1]), rowm[row1]);
        float ps0 = 0.0f, ps1 = 0.0f;
#pragma unroll
        for (int ni = 0; ni < 4; ni++) {
#pragma unroll
            for (int c = 0; c < 4; c++) {
                float p = __expf(sacc[ni][c] - ((c < 2) ? mx0 : mx1));
                sacc[ni][c] = p;
                if (c < 2) ps0 += p; else ps1 += p;
            }
        }
        ps0 += __shfl_xor_sync(0xffffffff, ps0, 1);
        ps0 += __shfl_xor_sync(0xffffffff, ps0, 2);
        ps1 += __shfl_xor_sync(0xffffffff, ps1, 1);
        ps1 += __shfl_xor_sync(0xffffffff, ps1, 2);
        if (tg == 0) {
            wsum[nh * 64 + row0] = ps0;
            wsum[nh * 64 + row1] = ps1;
        }
        float mxt = 0.0f, ft = 0.0f;
        if (t < 64) {
            mxt = fmaxf(fmaxf(wmax[t], wmax[64 + t]), rowm[t]);
            ft  = __expf(rowm[t] - mxt);
            rowf[t] = ft;
        }
        __syncthreads();

        if (t < 64) {
            rowl[t] = rowl[t] * ft + wsum[t] + wsum[64 + t];
            rowm[t] = mxt;
        }

        {
            float f0 = rowf[row0], f1 = rowf[row1];
#pragma unroll
            for (int ni = 0; ni < 8; ni++) {
                o[ni][0] *= f0; o[ni][1] *= f0;
                o[ni][2] *= f1; o[ni][3] *= f1;
            }
        }
#pragma unroll
        for (int ni = 0; ni < 4; ni++) {
            const int colb = wn + ni * 8 + 2 * tg;
            *(float2*)&Ss[row0 * LDSS_ + colb] = make_float2(sacc[ni][0], sacc[ni][1]);
            *(float2*)&Ss[row1 * LDSS_ + colb] = make_float2(sacc[ni][2], sacc[ni][3]);
        }
        const float* vptr = g_v + ((size_t)(b * S_ + kblk * BS_)) * KVDIM_ + kvh * D_;
        for (int i4 = t; i4 < 64 * 32; i4 += 256) {
            int r = i4 >> 5, d4 = (i4 & 31) << 2;
            *(float4*)&KVs[r * LDQ_ + d4] = *(const float4*)(vptr + (size_t)r * KVDIM_ + d4);
        }
        __syncthreads();

#pragma unroll
        for (int ks = 0; ks < 8; ks++) {
            const int kb = ks * 8;
            uint32_t ahi[4], alo[4];
            split_tf32(Ss[row0 * LDSS_ + kb + tg],     ahi[0], alo[0]);
            split_tf32(Ss[row1 * LDSS_ + kb + tg],     ahi[1], alo[1]);
            split_tf32(Ss[row0 * LDSS_ + kb + tg + 4], ahi[2], alo[2]);
            split_tf32(Ss[row1 * LDSS_ + kb + tg + 4], ahi[3], alo[3]);
#pragma unroll
            for (int ni = 0; ni < 8; ni++) {
                const int n = wn2 + ni * 8 + g;
                uint32_t bhi[2], blo[2];
                split_tf32(KVs[(kb + tg) * LDQ_ + n],     bhi[0], blo[0]);
                split_tf32(KVs[(kb + tg + 4) * LDQ_ + n], bhi[1], blo[1]);
                mma_tf32(o[ni], ahi, bhi);
                mma_tf32(o[ni], ahi, blo);
                mma_tf32(o[ni], alo, bhi);
            }
        }
        __syncthreads();
    }

    // finalize: divide by denom, write out as tf32 bits (feeds O projection)
    const float invl0 = 1.0f / rowl[row0];
    const float invl1 = 1.0f / rowl[row1];
    float* ob0 = g_attn + ((size_t)(b * S_ + qid * BS_ + row0)) * QDIM_ + h * D_;
    float* ob1 = g_attn + ((size_t)(b * S_ + qid * BS_ + row1)) * QDIM_ + h * D_;
#pragma unroll
    for (int ni = 0; ni < 8; ni++) {
        const int col = wn2 + ni * 8 + 2 * tg;
        *(uint2*)(ob0 + col) = make_uint2(f2tf32(o[ni][0] * invl0),
                                          f2tf32(o[ni][1] * invl0));
        *(uint2*)(ob1 + col) = make_uint2(f2tf32(o[ni][2] * invl1),
                                          f2tf32(o[ni][3] * invl1));
    }
}

// ---------------- host launcher -------------------------------------------
extern "C" void kernel_launch(void* const* d_in, const int* in_sizes, int n_in,
                              void* d_out, int out_size)
{
    const float* X    = (const float*)d_in[0];
    const float* cosp = (const float*)d_in[1];
    const float* sinp = (const float*)d_in[2];
    const float* Wq   = (const float*)d_in[3];
    const float* Wk   = (const float*)d_in[4];
    const float* Wv   = (const float*)d_in[5];
    const float* Wo   = (const float*)d_in[6];
    float* out = (float*)d_out;

    float *qb, *kb, *vb, *ab;
    uint32_t *xt, *wt;
    cudaGetSymbolAddress((void**)&qb, g_q);
    cudaGetSymbolAddress((void**)&kb, g_k);
    cudaGetSymbolAddress((void**)&vb, g_v);
    cudaGetSymbolAddress((void**)&ab, g_attn);
    cudaGetSymbolAddress((void**)&xt, g_xt);
    cudaGetSymbolAddress((void**)&wt, g_wt);

    cudaFuncSetAttribute(attn_kernel,
                         cudaFuncAttributeMaxDynamicSharedMemorySize,
                         AT_SMEM_BYTES);
    cudaFuncSetAttribute(gemm_tf32_pipe,
                         cudaFuncAttributeMaxDynamicSharedMemorySize,
                         GEMM_SMEM_BYTES);

    const int ct = 256;
    // X -> tf32
    cvt_tf32_kernel<<<(NTOK_ * H_ / 4 + ct - 1) / ct, ct>>>(X, xt, NTOK_ * H_ / 4);

    // Q projection
    cvt_tf32_kernel<<<(QDIM_ * H_ / 4 + ct - 1) / ct, ct>>>(Wq, wt, QDIM_ * H_ / 4);
    gemm_tf32_pipe<<<dim3(QDIM_ / 128, NTOK_ / 128), 256, GEMM_SMEM_BYTES>>>(
        xt, wt, qb, NTOK_, QDIM_, H_);

    // K projection
    cvt_tf32_kernel<<<(KVDIM_ * H_ / 4 + ct - 1) / ct, ct>>>(Wk, wt, KVDIM_ * H_ / 4);
    gemm_tf32_pipe<<<dim3(KVDIM_ / 128, NTOK_ / 128), 256, GEMM_SMEM_BYTES>>>(
        xt, wt, kb, NTOK_, KVDIM_, H_);

    // V projection
    cvt_tf32_kernel<<<(KVDIM_ * H_ / 4 + ct - 1) / ct, ct>>>(Wv, wt, KVDIM_ * H_ / 4);
    gemm_tf32_pipe<<<dim3(KVDIM_ / 128, NTOK_ / 128), 256, GEMM_SMEM_BYTES>>>(
        xt, wt, vb, NTOK_, KVDIM_, H_);

    // RoPE on Q and K
    int rope_total = NTOK_ * (NH_ + NKV_) * (D_ / 2);
    rope_kernel<<<(rope_total + 255) / 256, 256>>>(cosp, sinp);

    // block-sparse attention (writes tf32 bits to g_attn)
    attn_kernel<<<dim3(KB_, NH_, B_), 256, AT_SMEM_BYTES>>>();

    // O projection
    cvt_tf32_kernel<<<(H_ * QDIM_ / 4 + ct - 1) / ct, ct>>>(Wo, wt, H_ * QDIM_ / 4);
    gemm_tf32_pipe<<<dim3(H_ / 128, NTOK_ / 128), 256, GEMM_SMEM_BYTES>>>(
        (const uint32_t*)ab, wt, out, NTOK_, H_, QDIM_);
}